// round 13
// baseline (speedup 1.0000x reference)
#include <cuda_runtime.h>
#include <cfloat>

#define BB 4
#define NN 4096
#define SS 1024
#define C1v 128
#define C2v 256
#define COv 128
#define KNNK 16
#define FEAT 384
#define MM (BB*NN)

// ---------------- scratch ------------------------------------------------------
static __device__ float g_p2t[BB*SS*C2v];
static __device__ float g_feat[MM*FEAT];
static __device__ float g_xpre[BB*COv*NN];
static __device__ float g_x[BB*COv*NN];
static __device__ float g_xt[MM*COv];
static __device__ float g_dx[MM*COv];
static __device__ float g_hr[BB*COv*NN];
static __device__ int   g_knn[MM*KNNK];
static __device__ float g_stats[4*COv];
static __device__ float g_ab[4*COv];

// ---------------- f32x2 helpers ------------------------------------------------
__device__ __forceinline__ unsigned long long dup2(float v){
    unsigned long long r; unsigned int u=__float_as_uint(v);
    asm("mov.b64 %0, {%1,%2};" : "=l"(r) : "r"(u), "r"(u));
    return r;
}
__device__ __forceinline__ unsigned long long fma2(unsigned long long a,
        unsigned long long b, unsigned long long c){
    unsigned long long d;
    asm("fma.rn.f32x2 %0, %1, %2, %3;" : "=l"(d) : "l"(a), "l"(b), "l"(c));
    return d;
}
__device__ __forceinline__ float2 unpack2(unsigned long long v){
    unsigned int lo,hi;
    asm("mov.b64 {%0,%1}, %2;" : "=r"(lo), "=r"(hi) : "l"(v));
    return make_float2(__uint_as_float(lo), __uint_as_float(hi));
}

// matched-to-reference squared norm / dot (separate rounding, no FMA contraction)
__device__ __forceinline__ float sq3(float x, float y, float z){
    return __fadd_rn(__fadd_rn(__fmul_rn(x,x),__fmul_rn(y,y)),__fmul_rn(z,z));
}
__device__ __forceinline__ float dot3(float ax,float ay,float az,float bx,float by,float bz){
    return __fadd_rn(__fadd_rn(__fmul_rn(ax,bx),__fmul_rn(ay,by)),__fmul_rn(az,bz));
}

// ---------------- zero stats ---------------------------------------------------
__global__ void k_zero() {
    int t = threadIdx.x;
    if (t < 4*COv) g_stats[t] = 0.f;
}

// ---------------- 32x32 tiled transpose ---------------------------------------
__global__ void k_transpose(const float* __restrict__ in, float* __restrict__ out,
                            int R, int Cn, int ostride) {
    __shared__ float tile[32][33];
    int b = blockIdx.z;
    int x0 = blockIdx.x*32, y0 = blockIdx.y*32;
    int tx = threadIdx.x, ty = threadIdx.y;
    const float* ip = in + (size_t)b*R*Cn;
    float* op = out + (size_t)b*Cn*ostride;
#pragma unroll
    for (int q = 0; q < 4; q++)
        tile[ty+q*8][tx] = ip[(size_t)(y0+ty+q*8)*Cn + x0+tx];
    __syncthreads();
#pragma unroll
    for (int q = 0; q < 4; q++)
        op[(size_t)(x0+ty+q*8)*ostride + y0+tx] = tile[tx][ty+q*8];
}

// ---------------- top-3 FARTHEST; 32 rows x 8 cols, grid 512 -------------------
__global__ __launch_bounds__(256) void k_top3(const float* __restrict__ xyz1,
                                              const float* __restrict__ xyz2,
                                              float* __restrict__ w3,
                                              int* __restrict__ i3) {
    __shared__ float4 c2[SS];           // 16 KB
    __shared__ float md[32*24];
    __shared__ int   mi[32*24];
    int t = threadIdx.x, b = blockIdx.y;
    for (int i = t; i < SS; i += 256) {
        const float* p = xyz2 + (size_t)(b*SS + i)*3;
        float x = p[0], y = p[1], z = p[2];
        c2[i] = make_float4(x, y, z, sq3(x,y,z));
    }
    __syncthreads();
    int row = t & 31, col = t >> 5;     // 8 cols x 128 candidates
    int n = blockIdx.x*32 + row;
    const float* q = xyz1 + (size_t)(b*NN + n)*3;
    float qx = q[0], qy = q[1], qz = q[2];
    float sn = sq3(qx,qy,qz);
    float d0 = -FLT_MAX, d1 = -FLT_MAX, d2 = -FLT_MAX;
    int i0 = 0, i1 = 0, i2 = 0;
    int j0 = col*128;
    for (int jj = 0; jj < 128; jj += 4) {
        float dd[4];
#pragma unroll
        for (int u = 0; u < 4; u++) {
            float4 f = c2[j0+jj+u];
            float dt = dot3(qx,qy,qz, f.x,f.y,f.z);
            dd[u] = __fsub_rn(__fadd_rn(sn, f.w), __fmul_rn(2.f, dt));
        }
#pragma unroll
        for (int u = 0; u < 4; u++) {
            float d = dd[u]; int idx = j0+jj+u;
            if (d > d2) {
                if (d > d1) {
                    d2 = d1; i2 = i1;
                    if (d > d0) { d1 = d0; i1 = i0; d0 = d; i0 = idx; }
                    else        { d1 = d;  i1 = idx; }
                } else { d2 = d; i2 = idx; }
            }
        }
    }
    int base = row*24 + col*3;
    md[base] = d0; md[base+1] = d1; md[base+2] = d2;
    mi[base] = i0; mi[base+1] = i1; mi[base+2] = i2;
    __syncthreads();
    if (col == 0) {
        float e0 = -FLT_MAX, e1 = -FLT_MAX, e2 = -FLT_MAX;
        int a0 = 0, a1 = 0, a2 = 0;
#pragma unroll
        for (int e = 0; e < 24; e++) {
            float d = md[row*24+e]; int ii = mi[row*24+e];
            if (d > e2) {
                if (d > e1) {
                    e2 = e1; a2 = a1;
                    if (d > e0) { e1 = e0; a1 = a0; e0 = d; a0 = ii; }
                    else        { e1 = d;  a1 = ii; }
                } else { e2 = d; a2 = ii; }
            }
        }
        float r0 = __fdiv_rn(1.f, __fadd_rn(e0, 1e-8f));
        float r1 = __fdiv_rn(1.f, __fadd_rn(e1, 1e-8f));
        float r2 = __fdiv_rn(1.f, __fadd_rn(e2, 1e-8f));
        float ws = __fadd_rn(__fadd_rn(r0, r1), r2);
        int m = b*NN + n;
        w3[m*3]   = __fdiv_rn(r0, ws);
        w3[m*3+1] = __fdiv_rn(r1, ws);
        w3[m*3+2] = __fdiv_rn(r2, ws);
        i3[m*3] = a0; i3[m*3+1] = a1; i3[m*3+2] = a2;
    }
}

// ---------------- interp -> feat[...,128:384] ----------------------------------
__global__ void k_interp(const float* __restrict__ w3, const int* __restrict__ i3) {
    int idx = blockIdx.x*256 + threadIdx.x;
    int m = idx >> 8, c = idx & 255;
    int b = m >> 12;
    const int*   ii = i3 + m*3;
    const float* ww = w3 + m*3;
    const float* base = g_p2t + (size_t)b*SS*C2v + c;
    float v =            ww[0]*base[(size_t)ii[0]*C2v];
    v = fmaf(ww[1], base[(size_t)ii[1]*C2v], v);
    v = fmaf(ww[2], base[(size_t)ii[2]*C2v], v);
    g_feat[(size_t)m*FEAT + C1v + c] = v;
}

// ------- double-buffered GEMM, f32x2 packed FMA, fused bias/relu/stats --------
template<int KT, bool RELU>
__global__ __launch_bounds__(256) void k_gemm(const float* __restrict__ A,
                                              const float* __restrict__ W,
                                              const float* __restrict__ bias,
                                              float* __restrict__ outp,
                                              float* __restrict__ stats) {
    constexpr int BM = 64, BO = 64, BK = 16;
    __shared__ __align__(16) float As[2][BK][BM+4];
    __shared__ __align__(16) float Ws[2][BK][BO+4];
    __shared__ float ssum[BO], ssq[BO];
    int t = threadIdx.x;
    int m0 = blockIdx.x*BM, o0 = blockIdx.y*BO;
    if (t < BO) { ssum[t] = 0.f; ssq[t] = 0.f; }
    int trow = t >> 4, tcol = t & 15;
    int lkk = t & 15, lmm = t >> 4;
    const float* Ap = A + (size_t)(m0+lmm)*KT + lkk;
    const float* Wp = W + (size_t)(o0+lmm)*KT + lkk;
    float pa[4], pw[4];
#pragma unroll
    for (int qd = 0; qd < 4; qd++) {
        pa[qd] = Ap[(size_t)qd*16*KT];
        pw[qd] = Wp[(size_t)qd*16*KT];
    }
#pragma unroll
    for (int qd = 0; qd < 4; qd++) {
        As[0][lkk][lmm+qd*16] = pa[qd];
        Ws[0][lkk][lmm+qd*16] = pw[qd];
    }
    __syncthreads();
    unsigned long long acc[4][2];
#pragma unroll
    for (int i = 0; i < 4; i++) { acc[i][0] = 0ull; acc[i][1] = 0ull; }
    int p = 0;
    for (int k0 = 0; k0 < KT; k0 += BK) {
        bool more = (k0 + BK < KT);
        if (more) {
#pragma unroll
            for (int qd = 0; qd < 4; qd++) {
                pa[qd] = Ap[(size_t)(k0+BK) + (size_t)qd*16*KT];
                pw[qd] = Wp[(size_t)(k0+BK) + (size_t)qd*16*KT];
            }
        }
#pragma unroll
        for (int k = 0; k < BK; k++) {
            float4 av = *(const float4*)&As[p][k][trow*4];
            ulonglong2 wv = *(const ulonglong2*)&Ws[p][k][tcol*4];
            unsigned long long a0 = dup2(av.x), a1 = dup2(av.y),
                               a2 = dup2(av.z), a3 = dup2(av.w);
            acc[0][0] = fma2(a0, wv.x, acc[0][0]); acc[0][1] = fma2(a0, wv.y, acc[0][1]);
            acc[1][0] = fma2(a1, wv.x, acc[1][0]); acc[1][1] = fma2(a1, wv.y, acc[1][1]);
            acc[2][0] = fma2(a2, wv.x, acc[2][0]); acc[2][1] = fma2(a2, wv.y, acc[2][1]);
            acc[3][0] = fma2(a3, wv.x, acc[3][0]); acc[3][1] = fma2(a3, wv.y, acc[3][1]);
        }
        if (more) {
            p ^= 1;
#pragma unroll
            for (int qd = 0; qd < 4; qd++) {
                As[p][lkk][lmm+qd*16] = pa[qd];
                Ws[p][lkk][lmm+qd*16] = pw[qd];
            }
            __syncthreads();
        }
    }
    float vs[4][4];
#pragma unroll
    for (int i = 0; i < 4; i++) {
        float2 lo = unpack2(acc[i][0]);
        float2 hi = unpack2(acc[i][1]);
        vs[i][0] = lo.x; vs[i][1] = lo.y; vs[i][2] = hi.x; vs[i][3] = hi.y;
    }
    int n_base = (m0 & (NN-1)) + trow*4;
    int b = m0 >> 12;
#pragma unroll
    for (int j = 0; j < 4; j++) {
        int o = o0 + tcol*4 + j;
        float bv = bias[o];
        float s = 0.f, qs = 0.f;
        float w[4];
#pragma unroll
        for (int i = 0; i < 4; i++) {
            float v = vs[i][j] + bv;
            if (RELU) v = fmaxf(v, 0.f);
            w[i] = v; s += v; qs = fmaf(v, v, qs);
        }
        float4 v4; v4.x = w[0]; v4.y = w[1]; v4.z = w[2]; v4.w = w[3];
        *(float4*)(outp + ((size_t)(b*COv + o)*NN) + n_base) = v4;
        atomicAdd(&ssum[tcol*4+j], s);
        atomicAdd(&ssq[tcol*4+j], qs);
    }
    __syncthreads();
    if (t < BO) {
        atomicAdd(&stats[o0 + t],       ssum[t]);
        atomicAdd(&stats[COv + o0 + t], ssq[t]);
    }
}

// ---------------- BN finalize --------------------------------------------------
__global__ void k_finalize(const float* __restrict__ stats,
                           const float* __restrict__ gamma,
                           const float* __restrict__ beta,
                           float* __restrict__ ab) {
    int t = threadIdx.x;
    if (t < COv) {
        float invn = 1.f / (float)MM;
        float mean = stats[t] * invn;
        float var  = fmaf(-mean, mean, stats[COv + t] * invn);
        float a = gamma[t] * rsqrtf(var + 1e-5f);
        ab[t] = a;
        ab[COv + t] = beta[t] - mean*a;
    }
}

// ---------------- BN+ReLU apply + transposed copy ------------------------------
__global__ void k_bnrelu_tr() {
    __shared__ float tile[32][33];
    int b = blockIdx.z;
    int c0 = blockIdx.y*32, n0 = blockIdx.x*32;
    int tx = threadIdx.x, ty = threadIdx.y;
    const float* A = g_xpre + (size_t)b*COv*NN;
    float* X = g_x + (size_t)b*COv*NN;
#pragma unroll
    for (int qd = 0; qd < 4; qd++) {
        int c = c0 + ty + qd*8;
        float v = fmaf(g_ab[c], A[(size_t)c*NN + n0+tx], g_ab[COv + c]);
        v = fmaxf(v, 0.f);
        X[(size_t)c*NN + n0+tx] = v;
        tile[ty+qd*8][tx] = v;
    }
    __syncthreads();
#pragma unroll
    for (int qd = 0; qd < 4; qd++) {
        int n = n0 + ty + qd*8;
        g_xt[((size_t)(b*NN) + n)*COv + c0 + tx] = tile[tx][ty+qd*8];
    }
}

// ---------------- self-KNN top-16; 32 rows x 8 cols, grid 512 ------------------
__global__ __launch_bounds__(256) void k_knn(const float* __restrict__ xyz1) {
    union SH {
        float4 cand[2048];
        struct { float d[4096]; int i[4096]; } mg;
    };
    __shared__ SH sh;
    int t = threadIdx.x, b = blockIdx.y;
    int row = t & 31, col = t >> 5;
    int n = blockIdx.x*32 + row;
    const float* q = xyz1 + (size_t)(b*NN + n)*3;
    float qx = q[0], qy = q[1], qz = q[2];
    float sn = sq3(qx,qy,qz);
    float bd[16]; int bi[16];
#pragma unroll
    for (int r = 0; r < 16; r++) { bd[r] = FLT_MAX; bi[r] = 0; }
    float cm = FLT_MAX;
    for (int ch = 0; ch < 2; ch++) {
        __syncthreads();
        for (int i = t; i < 2048; i += 256) {
            const float* p = xyz1 + (size_t)(b*NN + ch*2048 + i)*3;
            float x = p[0], y = p[1], z = p[2];
            sh.cand[i] = make_float4(x, y, z, sq3(x,y,z));
        }
        __syncthreads();
        int base = col*256;
        int gbase = ch*2048 + base;
        for (int jj = 0; jj < 256; jj += 4) {
            float dd[4];
#pragma unroll
            for (int u = 0; u < 4; u++) {
                float4 f = sh.cand[base+jj+u];
                float dt = dot3(qx,qy,qz, f.x,f.y,f.z);
                dd[u] = __fsub_rn(__fadd_rn(sn, f.w), __fmul_rn(2.f, dt));
            }
#pragma unroll
            for (int u = 0; u < 4; u++) {
                float d = dd[u];
                if (d < cm) {
                    bool done = false;
#pragma unroll
                    for (int r = 0; r < 16; r++)
                        if (!done && bd[r] == cm) { bd[r] = d; bi[r] = gbase+jj+u; done = true; }
                    cm = bd[0];
#pragma unroll
                    for (int r = 1; r < 16; r++) cm = fmaxf(cm, bd[r]);
                }
            }
        }
    }
    __syncthreads();
#pragma unroll
    for (int r = 0; r < 16; r++) {
        sh.mg.d[row*128 + col*16 + r] = bd[r];
        sh.mg.i[row*128 + col*16 + r] = bi[r];
    }
    __syncthreads();
    if (col == 0) {
        float fd[16]; int fi[16];
#pragma unroll
        for (int r = 0; r < 16; r++) { fd[r] = FLT_MAX; fi[r] = 0; }
        float fm = FLT_MAX;
        for (int e = 0; e < 128; e++) {
            float d = sh.mg.d[row*128 + e];
            int  id = sh.mg.i[row*128 + e];
            if (d < fm) {
                bool done = false;
#pragma unroll
                for (int r = 0; r < 16; r++)
                    if (!done && fd[r] == fm) { fd[r] = d; fi[r] = id; done = true; }
                fm = fd[0];
#pragma unroll
                for (int r = 1; r < 16; r++) fm = fmaxf(fm, fd[r]);
            }
        }
        int* kp = g_knn + (size_t)(b*NN + n)*KNNK;
#pragma unroll
        for (int r = 0; r < 16; r++) kp[r] = fi[r];
    }
}

// ---------------- dx = sum of 16 NN rows minus self ----------------------------
__global__ void k_gather() {
    int idx = blockIdx.x*256 + threadIdx.x;
    int m = idx >> 5, c4 = idx & 31;
    int b = m >> 12;
    const int* kn = g_knn + (size_t)m*KNNK;
    const float4* xt = (const float4*)g_xt;
    float4 s = xt[(size_t)m*32 + c4];
    float ax = -s.x, ay = -s.y, az = -s.z, aw = -s.w;
#pragma unroll
    for (int j = 0; j < 16; j++) {
        int id = kn[j];
        float4 v = xt[((size_t)(b << 12) + id)*32 + c4];
        ax += v.x; ay += v.y; az += v.z; aw += v.w;
    }
    ((float4*)g_dx)[(size_t)m*32 + c4] = make_float4(ax, ay, az, aw);
}

// ---------------- out = x + bn2(hr) --------------------------------------------
__global__ void k_final(float* __restrict__ out) {
    int idx = blockIdx.x*256 + threadIdx.x;
    int c = (idx >> 12) & (COv-1);
    out[idx] = g_x[idx] + fmaf(g_ab[2*COv + c], g_hr[idx], g_ab[3*COv + c]);
}

// ---------------- launch -------------------------------------------------------
static __device__ float g_w3[MM*3];
static __device__ int   g_i3[MM*3];

extern "C" void kernel_launch(void* const* d_in, const int* in_sizes, int n_in,
                              void* d_out, int out_size) {
    const float* xyz1    = (const float*)d_in[0];
    const float* xyz2    = (const float*)d_in[1];
    const float* points1 = (const float*)d_in[2];
    const float* points2 = (const float*)d_in[3];
    const float* fuse_w  = (const float*)d_in[4];
    const float* fuse_b  = (const float*)d_in[5];
    const float* fuse_g  = (const float*)d_in[6];
    const float* fuse_be = (const float*)d_in[7];
    const float* lu_w    = (const float*)d_in[8];
    const float* lu_b    = (const float*)d_in[9];
    const float* lu_g    = (const float*)d_in[10];
    const float* lu_be   = (const float*)d_in[11];
    float* out = (float*)d_out;

    float *p2t, *feat, *xpre, *stats, *ab, *hr, *dx_g, *w3;
    int *i3;
    cudaGetSymbolAddress((void**)&p2t,  g_p2t);
    cudaGetSymbolAddress((void**)&feat, g_feat);
    cudaGetSymbolAddress((void**)&xpre, g_xpre);
    cudaGetSymbolAddress((void**)&stats,g_stats);
    cudaGetSymbolAddress((void**)&ab,   g_ab);
    cudaGetSymbolAddress((void**)&hr,   g_hr);
    cudaGetSymbolAddress((void**)&dx_g, g_dx);
    cudaGetSymbolAddress((void**)&w3,   g_w3);
    cudaGetSymbolAddress((void**)&i3,   g_i3);

    k_zero<<<1, 512>>>();
    k_transpose<<<dim3(SS/32, C2v/32, BB), dim3(32,8)>>>(points2, p2t, C2v, SS, C2v);
    k_transpose<<<dim3(NN/32, C1v/32, BB), dim3(32,8)>>>(points1, feat, C1v, NN, FEAT);
    k_top3<<<dim3(NN/32, BB), 256>>>(xyz1, xyz2, w3, i3);
    k_interp<<<(MM*C2v)/256, 256>>>(w3, i3);
    k_gemm<FEAT, false><<<dim3(MM/64, COv/64), 256>>>(feat, fuse_w, fuse_b, xpre, stats);
    k_finalize<<<1, 128>>>(stats, fuse_g, fuse_be, ab);
    k_bnrelu_tr<<<dim3(NN/32, COv/32, BB), dim3(32,8)>>>();
    k_knn<<<dim3(NN/32, BB), 256>>>(xyz1);
    k_gather<<<(MM*32)/256, 256>>>();
    k_gemm<COv, true><<<dim3(MM/64, COv/64), 256>>>(dx_g, lu_w, lu_b, hr, stats + 2*COv);
    k_finalize<<<1, 128>>>(stats + 2*COv, lu_g, lu_be, ab + 2*COv);
    k_final<<<(BB*COv*NN)/256, 256>>>(out);
    (void)in_sizes; (void)n_in; (void)out_size;
}